// round 6
// baseline (speedup 1.0000x reference)
#include <cuda_runtime.h>

// YOLOv2 region loss — 1 cell/thread (max occupancy), select-free mask test,
// fully warp-cooperative rare path (argmax over 50 GTs + 80-class NLL).
// B=16, A=5, C=80, H=W=64, N_GT=50, STRIDE=16, THRESH=0.6

#define NA 5
#define NC 80
#define NGT 50
#define HW 4096
#define CH 85
#define BLK 128
#define NBLOCKS 2560     // 327680 / 128
#define FULL 0xffffffffu

__device__ double g_part[NBLOCKS];
__device__ unsigned int g_flag;   // zero-init; last block resets each launch

__global__ __launch_bounds__(BLK) void rl_loss_kernel(
    const float* __restrict__ outp,
    const float* __restrict__ target,
    const float* __restrict__ anchors,
    float* __restrict__ out)
{
    __shared__ float4 s_box[NGT];      // x1,y1,x2,y2
    __shared__ float  s_m3sa[NGT];     // -3 * gt_area  (phase-1 key)
    __shared__ float  s_sa[NGT];       // exact gt_area (phase-2)
    __shared__ float4 s_gt[NGT];       // cx,cy,w,h
    __shared__ float  s_cls[NGT];
    __shared__ double s_red[4];
    __shared__ int    s_last;

    const int tid  = threadIdx.x;
    const int lane = tid & 31;
    const int wid  = tid >> 5;
    const int cell = blockIdx.x * BLK + tid;
    const int ba   = cell >> 12;               // same for whole block (128 | 4096)
    const int b    = ba / NA;
    const int a    = ba - b * NA;
    const int hw   = cell & (HW - 1);
    const int h    = hw >> 6;
    const int w    = hw & 63;

    if (tid < NGT) {
        const float* t = target + ((size_t)b * NGT + tid) * 5;
        float cls = t[0], cx = t[1], cy = t[2], gw = t[3], gh = t[4];
        float x1 = cx - gw * 0.5f, y1 = cy - gh * 0.5f;
        float x2 = cx + gw * 0.5f, y2 = cy + gh * 0.5f;
        float sa = (x2 - x1) * (y2 - y1);
        s_box[tid]  = make_float4(x1, y1, x2, y2);
        s_m3sa[tid] = -3.0f * sa;
        s_sa[tid]   = sa;
        s_gt[tid]   = make_float4(cx, cy, gw, gh);
        s_cls[tid]  = cls;
    }
    __syncthreads();

    const float aw = anchors[2 * a];
    const float ah = anchors[2 * a + 1];
    const float* base = outp + ((size_t)ba * CH) * HW + hw;

    const float t0 = base[0];
    const float t1 = base[HW];
    const float t2 = base[2 * HW];
    const float t3 = base[3 * HW];
    const float conf = base[4 * HW];

    const float sx = __fdividef(1.0f, 1.0f + __expf(-t0));
    const float sy = __fdividef(1.0f, 1.0f + __expf(-t1));
    const float pxc = (sx + (float)w) * 16.0f;
    const float pyc = (sy + (float)h) * 16.0f;
    const float pw = __expf(t2) * aw;
    const float ph = __expf(t3) * ah;

    const float px1 = pxc - pw * 0.5f, py1 = pyc - ph * 0.5f;
    const float px2 = pxc + pw * 0.5f, py2 = pyc + ph * 0.5f;
    const float paeps = (px2 - px1) * (py2 - py1) + 1e-6f;   // pred_area + eps
    const float c3pe  = 3.0f * paeps;

    // ---- Phase 1: existence test.  iou_n > 0.6  <=>  8*I_n - 3*Sg_n > 3*(pa+eps)
    float mk = -1e30f;
#pragma unroll 10
    for (int n = 0; n < NGT; n++) {
        float4 bx = s_box[n];
        float cw = fminf(bx.z, px2) - fmaxf(bx.x, px1);
        float ch = fminf(bx.w, py2) - fmaxf(bx.y, py1);
        float I  = fmaxf(cw, 0.0f) * fmaxf(ch, 0.0f);
        mk = fmaxf(mk, fmaf(I, 8.0f, s_m3sa[n]));
    }
    const bool msk = (mk > c3pe);

    float loss = msk ? 0.0f : conf * conf;

    // ---- Phase 2 (rare, warp-cooperative): exact argmax + coord/conf/class loss.
    const float* clwarp = outp + ((size_t)ba * CH + 5) * HW
                        + ((blockIdx.x * BLK + (wid << 5)) & (HW - 1));
    unsigned bal = __ballot_sync(FULL, msk);
    while (bal) {
        const int src = __ffs(bal) - 1;
        bal &= bal - 1;

        // broadcast owner's pred box
        const float qx1 = __shfl_sync(FULL, px1, src);
        const float qy1 = __shfl_sync(FULL, py1, src);
        const float qx2 = __shfl_sync(FULL, px2, src);
        const float qy2 = __shfl_sync(FULL, py2, src);
        const float qpa = __shfl_sync(FULL, paeps, src);

        // lanes split the 50 GTs: n = lane, and n = lane+32 (lane < 18).
        // cross-multiplied compare (monotone-equiv to iou = I/(S-I); smaller
        // index wins ties, matching first-occurrence argmax).
        float bI, bS; int bidx;
        {
            float4 bx = s_box[lane];
            float cw = fminf(bx.z, qx2) - fmaxf(bx.x, qx1);
            float ch = fminf(bx.w, qy2) - fmaxf(bx.y, qy1);
            bI = fmaxf(cw, 0.0f) * fmaxf(ch, 0.0f);
            bS = s_sa[lane] + qpa;
            bidx = lane;
        }
        if (lane < NGT - 32) {
            int n2 = lane + 32;
            float4 bx = s_box[n2];
            float cw = fminf(bx.z, qx2) - fmaxf(bx.x, qx1);
            float ch = fminf(bx.w, qy2) - fmaxf(bx.y, qy1);
            float I2 = fmaxf(cw, 0.0f) * fmaxf(ch, 0.0f);
            float S2 = s_sa[n2] + qpa;
            if (I2 * bS > bI * S2) { bI = I2; bS = S2; bidx = n2; }
        }
        #pragma unroll
        for (int off = 16; off; off >>= 1) {
            float oI = __shfl_down_sync(FULL, bI, off);
            float oS = __shfl_down_sync(FULL, bS, off);
            int   oi = __shfl_down_sync(FULL, bidx, off);
            float l = oI * bS, r = bI * oS;
            if (l > r || (l == r && oi < bidx)) { bI = oI; bS = oS; bidx = oi; }
        }
        bidx = __shfl_sync(FULL, bidx, 0);

        // cooperative class logsumexp for the owner's cell (80 = 32+32+16)
        const float* cl = clwarp + src;
        float s = __expf(cl[(size_t)lane * HW])
                + __expf(cl[(size_t)(lane + 32) * HW]);
        if (lane < 16) s += __expf(cl[(size_t)(lane + 64) * HW]);
        #pragma unroll
        for (int off = 16; off; off >>= 1)
            s += __shfl_down_sync(FULL, s, off);
        s = __shfl_sync(FULL, s, 0);

        if (lane == src) {       // owner accumulates; its own base/t0..t3/conf
            float4 g = s_gt[bidx];
            float d0 = t0 - g.x;
            float d1 = t1 - g.y;
            float d2 = t2 - g.z;
            float d3 = t3 - g.w;
            float dc = 5.0f * conf - 5.0f;
            int idx = (int)s_cls[bidx];
            loss += d0 * d0 + d1 * d1 + d2 * d2 + d3 * d3 + dc * dc
                  + __logf(s) - cl[(size_t)idx * HW];
        }
    }

    // block reduction in double
    double v = (double)loss;
    #pragma unroll
    for (int off = 16; off; off >>= 1)
        v += __shfl_down_sync(FULL, v, off);

    if (lane == 0) s_red[wid] = v;
    __syncthreads();
    if (tid < 32) {
        v = (lane < 4) ? s_red[lane] : 0.0;
        v += __shfl_down_sync(FULL, v, 2);
        v += __shfl_down_sync(FULL, v, 1);
    }

    // last-block-reduces (single launch, graph-replay safe)
    if (tid == 0) {
        g_part[blockIdx.x] = v;
        __threadfence();
        unsigned int done = atomicAdd(&g_flag, 1u);
        s_last = (done == NBLOCKS - 1);
    }
    __syncthreads();

    if (s_last) {
        double t = 0.0;
        for (int i = tid; i < NBLOCKS; i += BLK)
            t += g_part[i];
        #pragma unroll
        for (int off = 16; off; off >>= 1)
            t += __shfl_down_sync(FULL, t, off);
        if (lane == 0) s_red[wid] = t;
        __syncthreads();
        if (tid == 0) {
            double tot = s_red[0] + s_red[1] + s_red[2] + s_red[3];
            out[0] = (float)tot;
            atomicExch(&g_flag, 0u);
        }
    }
}

extern "C" void kernel_launch(void* const* d_in, const int* in_sizes, int n_in,
                              void* d_out, int out_size)
{
    const float* outp    = (const float*)d_in[0];
    const float* target  = (const float*)d_in[1];
    const float* anchors = (const float*)d_in[2];
    float* out = (float*)d_out;

    rl_loss_kernel<<<NBLOCKS, BLK>>>(outp, target, anchors, out);
}

// round 7
// speedup vs baseline: 1.3007x; 1.3007x over previous
#include <cuda_runtime.h>

// YOLOv2 region loss — CPT=2 (best amortization, R5) + fully warp-cooperative
// rare path for argmax and class-NLL (R6). B=16,A=5,C=80,H=W=64,NGT=50.

#define NA 5
#define NC 80
#define NGT 50
#define HW 4096
#define CH 85
#define CPT 2
#define BLK 256
#define NBLOCKS 640      // 327680 / (256*2)
#define FULL 0xffffffffu

__device__ double g_part[NBLOCKS];
__device__ unsigned int g_flag;   // zero-init; last block resets each launch

__global__ __launch_bounds__(BLK) void rl_loss_kernel(
    const float* __restrict__ outp,
    const float* __restrict__ target,
    const float* __restrict__ anchors,
    float* __restrict__ out)
{
    __shared__ float4 s_box[NGT];      // x1,y1,x2,y2
    __shared__ float  s_m3sa[NGT];     // -3 * gt_area  (phase-1 key)
    __shared__ float  s_sa[NGT];       // exact gt_area (phase-2)
    __shared__ float4 s_gt[NGT];       // cx,cy,w,h
    __shared__ float  s_cls[NGT];
    __shared__ double s_red[8];
    __shared__ int    s_last;

    const int tid   = threadIdx.x;
    const int lane  = tid & 31;
    const int wid   = tid >> 5;
    const int cell0 = blockIdx.x * (BLK * CPT) + tid;   // second cell: +256
    const int ba    = cell0 >> 12;              // same for both cells (512 | 4096)
    const int b     = ba / NA;
    const int a     = ba - b * NA;
    const int hw0   = cell0 & (HW - 1);

    if (tid < NGT) {
        const float* t = target + ((size_t)b * NGT + tid) * 5;
        float cls = t[0], cx = t[1], cy = t[2], gw = t[3], gh = t[4];
        float x1 = cx - gw * 0.5f, y1 = cy - gh * 0.5f;
        float x2 = cx + gw * 0.5f, y2 = cy + gh * 0.5f;
        float sa = (x2 - x1) * (y2 - y1);
        s_box[tid]  = make_float4(x1, y1, x2, y2);
        s_m3sa[tid] = -3.0f * sa;
        s_sa[tid]   = sa;
        s_gt[tid]   = make_float4(cx, cy, gw, gh);
        s_cls[tid]  = cls;
    }
    __syncthreads();

    const float aw = anchors[2 * a];
    const float ah = anchors[2 * a + 1];
    const float* base = outp + ((size_t)ba * CH) * HW + hw0;

    float px1[CPT], py1[CPT], px2[CPT], py2[CPT];
    float paeps[CPT], conf[CPT], mk[CPT];

    #pragma unroll
    for (int c = 0; c < CPT; c++) {
        const float* bc = base + BLK * c;
        float t0 = bc[0];
        float t1 = bc[HW];
        float t2 = bc[2 * HW];
        float t3 = bc[3 * HW];
        conf[c]  = bc[4 * HW];
        int hwc = hw0 + BLK * c;
        int h = hwc >> 6, w = hwc & 63;
        float sx = __fdividef(1.0f, 1.0f + __expf(-t0));
        float sy = __fdividef(1.0f, 1.0f + __expf(-t1));
        float px = (sx + (float)w) * 16.0f;
        float py = (sy + (float)h) * 16.0f;
        float pw = __expf(t2) * aw;
        float ph = __expf(t3) * ah;
        px1[c] = px - pw * 0.5f;  py1[c] = py - ph * 0.5f;
        px2[c] = px + pw * 0.5f;  py2[c] = py + ph * 0.5f;
        paeps[c] = (px2[c] - px1[c]) * (py2[c] - py1[c]) + 1e-6f;
        mk[c]    = -1e30f;
    }

    // ---- Phase 1: existence test.  iou_n > 0.6 <=> 8*I_n - 3*Sg_n > 3*(pa+eps)
#pragma unroll 5
    for (int n = 0; n < NGT; n++) {
        float4 bx = s_box[n];
        float m3  = s_m3sa[n];
        #pragma unroll
        for (int c = 0; c < CPT; c++) {
            float cw = fminf(bx.z, px2[c]) - fmaxf(bx.x, px1[c]);
            float ch = fminf(bx.w, py2[c]) - fmaxf(bx.y, py1[c]);
            float I  = fmaxf(cw, 0.0f) * fmaxf(ch, 0.0f);
            mk[c] = fmaxf(mk[c], fmaf(I, 8.0f, m3));
        }
    }

    float loss = 0.0f;

    // ---- Phase 2 (rare, warp-cooperative): exact argmax + coord/conf/class.
    #pragma unroll
    for (int c = 0; c < CPT; c++) {
        const bool msk = (mk[c] > 3.0f * paeps[c]);
        if (!msk) loss += conf[c] * conf[c];

        unsigned bal = __ballot_sync(FULL, msk);
        if (bal == 0) continue;

        const float* clwarp = outp + ((size_t)ba * CH + 5) * HW
            + ((blockIdx.x * (BLK * CPT) + (wid << 5) + BLK * c) & (HW - 1));

        while (bal) {
            const int src = __ffs(bal) - 1;
            bal &= bal - 1;

            // broadcast owner's pred box
            const float qx1 = __shfl_sync(FULL, px1[c], src);
            const float qy1 = __shfl_sync(FULL, py1[c], src);
            const float qx2 = __shfl_sync(FULL, px2[c], src);
            const float qy2 = __shfl_sync(FULL, py2[c], src);
            const float qpa = __shfl_sync(FULL, paeps[c], src);

            // lanes split the 50 GTs (n = lane, n = lane+32 for lane<18);
            // cross-multiplied compare, smaller index wins ties (= first argmax)
            float bI, bS; int bidx;
            {
                float4 bx = s_box[lane];
                float cw = fminf(bx.z, qx2) - fmaxf(bx.x, qx1);
                float ch = fminf(bx.w, qy2) - fmaxf(bx.y, qy1);
                bI = fmaxf(cw, 0.0f) * fmaxf(ch, 0.0f);
                bS = s_sa[lane] + qpa;
                bidx = lane;
            }
            if (lane < NGT - 32) {
                int n2 = lane + 32;
                float4 bx = s_box[n2];
                float cw = fminf(bx.z, qx2) - fmaxf(bx.x, qx1);
                float ch = fminf(bx.w, qy2) - fmaxf(bx.y, qy1);
                float I2 = fmaxf(cw, 0.0f) * fmaxf(ch, 0.0f);
                float S2 = s_sa[n2] + qpa;
                if (I2 * bS > bI * S2) { bI = I2; bS = S2; bidx = n2; }
            }
            #pragma unroll
            for (int off = 16; off; off >>= 1) {
                float oI = __shfl_down_sync(FULL, bI, off);
                float oS = __shfl_down_sync(FULL, bS, off);
                int   oi = __shfl_down_sync(FULL, bidx, off);
                float l = oI * bS, r = bI * oS;
                if (l > r || (l == r && oi < bidx)) { bI = oI; bS = oS; bidx = oi; }
            }
            bidx = __shfl_sync(FULL, bidx, 0);

            // cooperative class logsumexp for owner's cell (80 = 32+32+16)
            const float* cl = clwarp + src;
            float s = __expf(cl[(size_t)lane * HW])
                    + __expf(cl[(size_t)(lane + 32) * HW]);
            if (lane < 16) s += __expf(cl[(size_t)(lane + 64) * HW]);
            #pragma unroll
            for (int off = 16; off; off >>= 1)
                s += __shfl_down_sync(FULL, s, off);
            s = __shfl_sync(FULL, s, 0);

            if (lane == src) {
                const float* bc = base + BLK * c;   // reload raw logits (L2-hot)
                float4 g = s_gt[bidx];
                float d0 = bc[0]      - g.x;
                float d1 = bc[HW]     - g.y;
                float d2 = bc[2 * HW] - g.z;
                float d3 = bc[3 * HW] - g.w;
                float dc = 5.0f * conf[c] - 5.0f;
                int idx = (int)s_cls[bidx];
                loss += d0 * d0 + d1 * d1 + d2 * d2 + d3 * d3 + dc * dc
                      + __logf(s) - cl[(size_t)idx * HW];
            }
        }
    }

    // block reduction in double
    double v = (double)loss;
    #pragma unroll
    for (int off = 16; off; off >>= 1)
        v += __shfl_down_sync(FULL, v, off);

    if (lane == 0) s_red[wid] = v;
    __syncthreads();
    if (tid < 32) {
        v = (lane < 8) ? s_red[lane] : 0.0;
        #pragma unroll
        for (int off = 4; off; off >>= 1)
            v += __shfl_down_sync(0xffu, v, off);
    }

    // last-block-reduces (single launch, graph-replay safe)
    if (tid == 0) {
        g_part[blockIdx.x] = v;
        __threadfence();
        unsigned int done = atomicAdd(&g_flag, 1u);
        s_last = (done == NBLOCKS - 1);
    }
    __syncthreads();

    if (s_last) {
        double t = 0.0;
        for (int i = tid; i < NBLOCKS; i += BLK)
            t += g_part[i];
        #pragma unroll
        for (int off = 16; off; off >>= 1)
            t += __shfl_down_sync(FULL, t, off);
        if (lane == 0) s_red[wid] = t;
        __syncthreads();
        if (tid == 0) {
            double tot = 0.0;
            #pragma unroll
            for (int i = 0; i < 8; i++) tot += s_red[i];
            out[0] = (float)tot;
            atomicExch(&g_flag, 0u);
        }
    }
}

extern "C" void kernel_launch(void* const* d_in, const int* in_sizes, int n_in,
                              void* d_out, int out_size)
{
    const float* outp    = (const float*)d_in[0];
    const float* target  = (const float*)d_in[1];
    const float* anchors = (const float*)d_in[2];
    float* out = (float*)d_out;

    rl_loss_kernel<<<NBLOCKS, BLK>>>(outp, target, anchors, out);
}